// round 2
// baseline (speedup 1.0000x reference)
#include <cuda_runtime.h>
#include <cuda_fp16.h>
#include <cstdint>

// ============================================================
// QuarotFP16Linear: out[t,o] = sum_i (x[t,i]*sx[t]) * ((w[o,i]-off[o,g])*ws[o,g])
// T=8192, I=4096, O=11008, G=32 (group=128)
//
// tcgen05 is unavailable (harness PTX target is compute_103, not 103a),
// so: prep kernels fold dequant into fp16 tensors, then a warp-level
// mma.sync.m16n8k16 GEMM with fp32 accumulation, cp.async 3-stage pipeline,
// SW128-swizzled smem + ldmatrix.
// ============================================================

#define TOKENS 8192
#define IN_F   4096
#define OUT_F  11008
#define GROUPS 32

#define BM 128
#define BN 128
#define BK 64                 // 64 fp16 = 128 bytes per row (SW128 atom)
#define KTILES (IN_F / BK)    // 64
#define STAGES 3

// fp16 operands, dequant pre-applied
__device__ __half g_Xh[(size_t)TOKENS * IN_F];   // 64 MB
__device__ __half g_Wh[(size_t)OUT_F  * IN_F];   // 90 MB

// ------------------------------------------------------------
// helpers
// ------------------------------------------------------------
__device__ __forceinline__ uint32_t smem_u32(const void* p) {
    uint32_t a;
    asm("{ .reg .u64 t; cvta.to.shared.u64 t, %1; cvt.u32.u64 %0, t; }" : "=r"(a) : "l"(p));
    return a;
}

__device__ __forceinline__ void cp_async16(uint32_t smem_dst, const void* gmem_src) {
    asm volatile("cp.async.cg.shared.global [%0], [%1], 16;"
                 :: "r"(smem_dst), "l"(gmem_src));
}
#define CP_ASYNC_COMMIT() asm volatile("cp.async.commit_group;" ::: "memory")
#define CP_ASYNC_WAIT1()  asm volatile("cp.async.wait_group 1;" ::: "memory")

__device__ __forceinline__ void ldsm_x4(uint32_t& r0, uint32_t& r1, uint32_t& r2,
                                        uint32_t& r3, uint32_t addr) {
    asm volatile("ldmatrix.sync.aligned.m8n8.x4.shared.b16 {%0,%1,%2,%3}, [%4];"
                 : "=r"(r0), "=r"(r1), "=r"(r2), "=r"(r3) : "r"(addr));
}

__device__ __forceinline__ void mma_16816(float* c, const uint32_t* a, const uint32_t* b) {
    asm volatile(
        "mma.sync.aligned.m16n8k16.row.col.f32.f16.f16.f32 "
        "{%0,%1,%2,%3}, {%4,%5,%6,%7}, {%8,%9}, {%0,%1,%2,%3};"
        : "+f"(c[0]), "+f"(c[1]), "+f"(c[2]), "+f"(c[3])
        : "r"(a[0]), "r"(a[1]), "r"(a[2]), "r"(a[3]), "r"(b[0]), "r"(b[1]));
}

// ------------------------------------------------------------
// Prep kernels: fold dequant into fp16 operand tensors
// ------------------------------------------------------------
__global__ void prep_x_kernel(const float* __restrict__ x,
                              const float* __restrict__ sx,
                              __half* __restrict__ xh) {
    size_t base = ((size_t)blockIdx.x * blockDim.x + threadIdx.x) * 4;
    int t = (int)(base >> 12);   // IN_F = 4096
    float s = __ldg(sx + t);
    float4 v = *reinterpret_cast<const float4*>(x + base);
    __half2* p = reinterpret_cast<__half2*>(xh + base);
    p[0] = __floats2half2_rn(v.x * s, v.y * s);
    p[1] = __floats2half2_rn(v.z * s, v.w * s);
}

__global__ void prep_w_kernel(const float* __restrict__ w,
                              const float* __restrict__ ws,
                              const float* __restrict__ wo,
                              __half* __restrict__ wh) {
    size_t base = ((size_t)blockIdx.x * blockDim.x + threadIdx.x) * 4;
    int o = (int)(base >> 12);
    int i = (int)(base & 4095);
    int g = i >> 7;              // group of 128; all 4 elems in same group
    float s = __ldg(ws + (size_t)o * GROUPS + g);
    float f = __ldg(wo + (size_t)o * GROUPS + g);
    float4 v = *reinterpret_cast<const float4*>(w + base);
    __half2* p = reinterpret_cast<__half2*>(wh + base);
    p[0] = __floats2half2_rn((v.x - f) * s, (v.y - f) * s);
    p[1] = __floats2half2_rn((v.z - f) * s, (v.w - f) * s);
}

// ------------------------------------------------------------
// GEMM: out[T,O] = Xh[T,K] · Wh[O,K]^T
// SMEM per stage: A tile 128x128B + B tile 128x128B = 32 KB, SW128 swizzled.
// Swizzled offset within a tile: row*128 + (bytecol ^ ((row&7)*16)).
// ------------------------------------------------------------
static constexpr int TILE_BYTES  = BM * 128;          // 16384
static constexpr int STAGE_BYTES = 2 * TILE_BYTES;    // 32768
static constexpr int SMEM_TOTAL  = STAGES * STAGE_BYTES;  // 98304

__device__ __forceinline__ void load_tile(const __half* __restrict__ A,
                                          const __half* __restrict__ B,
                                          int t0, int o0, int tid,
                                          uint32_t smem_base, int kt, int stage) {
    int row   = tid >> 1;            // 0..127
    int cbase = (tid & 1) * 4;       // 16B chunks 0-3 or 4-7
    int k0 = kt * BK;
    const __half* ga = A + (size_t)(t0 + row) * IN_F + k0 + cbase * 8;
    const __half* gb = B + (size_t)(o0 + row) * IN_F + k0 + cbase * 8;
    uint32_t sw = (uint32_t)((row & 7) * 16);
    uint32_t sa = smem_base + stage * STAGE_BYTES + row * 128;
    uint32_t sb = sa + TILE_BYTES;
#pragma unroll
    for (int c = 0; c < 4; ++c) {
        uint32_t off = ((uint32_t)((cbase + c) * 16)) ^ sw;
        cp_async16(sa + off, ga + c * 8);
        cp_async16(sb + off, gb + c * 8);
    }
}

__global__ void __launch_bounds__(256)
gemm_f16_kernel(const __half* __restrict__ A,    // [TOKENS, IN_F]
                const __half* __restrict__ B,    // [OUT_F, IN_F]
                float* __restrict__ out) {       // [TOKENS, OUT_F]
    extern __shared__ char smem[];
    uint32_t smem_base = smem_u32(smem);
    int tid  = threadIdx.x;
    int wid  = tid >> 5;
    int lane = tid & 31;
    int o0 = blockIdx.x * BN;
    int t0 = blockIdx.y * BM;

    int warp_m = wid & 1;    // 2 warps along M (64 rows each)
    int warp_n = wid >> 1;   // 4 warps along N (32 cols each)

    float acc[4][4][4];
#pragma unroll
    for (int mt = 0; mt < 4; ++mt)
#pragma unroll
        for (int nt = 0; nt < 4; ++nt)
#pragma unroll
            for (int j = 0; j < 4; ++j) acc[mt][nt][j] = 0.f;

    // Per-lane ldmatrix addressing (within a stage, before swizzle of k-column):
    // A 16x16 tile mt: lanes 0-15 -> rows, col +0; lanes 16-31 -> rows, col +8 halfs.
    uint32_t sw_mask = (uint32_t)((lane & 7) * 16);     // SW128 xor mask (bits 4-6)
    uint32_t a_row_off[4];
#pragma unroll
    for (int mt = 0; mt < 4; ++mt)
        a_row_off[mt] = (uint32_t)((warp_m * 64 + mt * 16 + (lane & 15)) * 128);
    uint32_t a_colsel = (uint32_t)((lane >> 4) * 16);   // bytes

    // B [N,K] tiles: ldmatrix.x4 covers two n8-tiles.
    // lanes 0-7: n+0..7 k+0 ; 8-15: n+0..7 k+8 ; 16-23: n+8..15 k+0 ; 24-31: n+8..15 k+8
    uint32_t b_row_off[2];
#pragma unroll
    for (int p = 0; p < 2; ++p)
        b_row_off[p] = (uint32_t)(TILE_BYTES +
            (warp_n * 32 + p * 16 + ((lane >> 4) * 8) + (lane & 7)) * 128);
    uint32_t b_colsel = (uint32_t)(((lane >> 3) & 1) * 16);

    // ---- pipeline prologue ----
    load_tile(A, B, t0, o0, tid, smem_base, 0, 0);
    CP_ASYNC_COMMIT();
    load_tile(A, B, t0, o0, tid, smem_base, 1, 1);
    CP_ASYNC_COMMIT();

    for (int kt = 0; kt < KTILES; ++kt) {
        CP_ASYNC_WAIT1();          // group kt complete (one group committed per iter)
        __syncthreads();

        // issue loads for kt+2 (into the stage freed at iter kt-1)
        if (kt + 2 < KTILES)
            load_tile(A, B, t0, o0, tid, smem_base, kt + 2, (kt + 2) % STAGES);
        CP_ASYNC_COMMIT();         // commit every iter (empty group ok) for uniform accounting

        uint32_t stage_base = smem_base + (kt % STAGES) * STAGE_BYTES;
#pragma unroll
        for (int ks = 0; ks < 4; ++ks) {
            uint32_t aa[4][4];
            uint32_t bb[4][2];
            uint32_t a_col = ((uint32_t)(ks * 32) + a_colsel) ^ sw_mask;
            uint32_t b_col = ((uint32_t)(ks * 32) + b_colsel) ^ sw_mask;
#pragma unroll
            for (int mt = 0; mt < 4; ++mt)
                ldsm_x4(aa[mt][0], aa[mt][1], aa[mt][2], aa[mt][3],
                        stage_base + a_row_off[mt] + a_col);
#pragma unroll
            for (int p = 0; p < 2; ++p)
                ldsm_x4(bb[p * 2][0], bb[p * 2][1], bb[p * 2 + 1][0], bb[p * 2 + 1][1],
                        stage_base + b_row_off[p] + b_col);
#pragma unroll
            for (int mt = 0; mt < 4; ++mt)
#pragma unroll
                for (int nt = 0; nt < 4; ++nt)
                    mma_16816(acc[mt][nt], aa[mt], bb[nt]);
        }
    }

    // ---- epilogue: direct global stores ----
    // c0,c1 -> row (lane>>2), cols 2*(lane&3)+{0,1}; c2,c3 -> row+8
    int r_base = t0 + warp_m * 64 + (lane >> 2);
    int c_base = o0 + warp_n * 32 + (lane & 3) * 2;
#pragma unroll
    for (int mt = 0; mt < 4; ++mt) {
#pragma unroll
        for (int nt = 0; nt < 4; ++nt) {
            float* p0 = out + (size_t)(r_base + mt * 16) * OUT_F + c_base + nt * 8;
            float* p1 = p0 + (size_t)8 * OUT_F;
            *reinterpret_cast<float2*>(p0) = make_float2(acc[mt][nt][0], acc[mt][nt][1]);
            *reinterpret_cast<float2*>(p1) = make_float2(acc[mt][nt][2], acc[mt][nt][3]);
        }
    }
}

// ------------------------------------------------------------
// Launch
// ------------------------------------------------------------
extern "C" void kernel_launch(void* const* d_in, const int* in_sizes, int n_in,
                              void* d_out, int out_size) {
    const float* x  = (const float*)d_in[0];   // [8192, 4096]
    const float* sx = (const float*)d_in[1];   // [8192, 1]
    const float* w  = (const float*)d_in[2];   // [11008, 4096]
    const float* ws = (const float*)d_in[3];   // [11008, 32]
    const float* wo = (const float*)d_in[4];   // [11008, 32]
    float* out = (float*)d_out;

    void* xh_p = nullptr;
    void* wh_p = nullptr;
    cudaGetSymbolAddress(&xh_p, g_Xh);
    cudaGetSymbolAddress(&wh_p, g_Wh);

    cudaFuncSetAttribute(gemm_f16_kernel,
                         cudaFuncAttributeMaxDynamicSharedMemorySize, SMEM_TOTAL);

    prep_x_kernel<<<(TOKENS * (size_t)IN_F / 4 + 255) / 256, 256>>>(x, sx, (__half*)xh_p);
    prep_w_kernel<<<(OUT_F  * (size_t)IN_F / 4 + 255) / 256, 256>>>(w, ws, wo, (__half*)wh_p);

    dim3 grid(OUT_F / BN, TOKENS / BM);   // (86, 64) — x along N keeps W panels L2-resident
    gemm_f16_kernel<<<grid, 256, SMEM_TOTAL>>>((const __half*)xh_p, (const __half*)wh_p, out);
}